// round 1
// baseline (speedup 1.0000x reference)
#include <cuda_runtime.h>
#include <math.h>
#include <stdint.h>

#define NP 500000
#define NQ 200000
#define CDIM 64
#define EMAX 1200000

// ------------------------- scratch (static device globals) -------------------------
__device__ float    g_hs [(size_t)NP * CDIM];   // hs = x_src @ Ws for current conv
__device__ float    g_hp1[(size_t)NP * CDIM];   // layer-0 person output
__device__ float    g_hq1[(size_t)NQ * CDIM];   // layer-0 product output
__device__ float    g_als[NP];
__device__ float    g_ald[NP];
__device__ unsigned g_m  [NP];                  // segment max (monotone-encoded float)
__device__ float    g_den[NP];
__device__ float    g_e  [EMAX];
__device__ float    g_wvec[CDIM];

// ------------------------- helpers -------------------------
// monotone float<->uint encoding so atomicMax on uint == float max (handles -0, negatives)
__device__ __forceinline__ unsigned fenc(float f) {
    unsigned u = __float_as_uint(f);
    return (u & 0x80000000u) ? ~u : (u | 0x80000000u);
}
__device__ __forceinline__ float fdec(unsigned u) {
    return __uint_as_float((u & 0x80000000u) ? (u & 0x7FFFFFFFu) : ~u);
}

// ------------------------- kernels -------------------------

// wvec[k] = sum_c Wd[k][c] * avd[c]   (one block, 64 threads)
__global__ void wvec_kernel(const float* __restrict__ Wd, const float* __restrict__ avd,
                            float* __restrict__ wvec) {
    int k = threadIdx.x;
    float s = 0.f;
    #pragma unroll
    for (int c = 0; c < CDIM; c++) s = fmaf(Wd[k * CDIM + c], avd[c], s);
    wvec[k] = s;
}

// H = X @ W  (X:[N,64], W:[64,64]), fused al_s = H @ avs epilogue.
// 128 threads/block, 128x64 output tile, 8x8 per thread.
__global__ __launch_bounds__(128) void gemm_als_kernel(
    const float* __restrict__ X, const float* __restrict__ W,
    const float* __restrict__ avs, float* __restrict__ H,
    float* __restrict__ als, int N)
{
    __shared__ float xT[64 * 128];   // [k][row] transposed, 32KB
    __shared__ float ws[64 * 64];    // [k][c], 16KB
    const int tid  = threadIdx.x;
    const int row0 = blockIdx.x * 128;

    // load W (4096 floats, 8 float4 per thread, coalesced)
    {
        const float4* Wv = (const float4*)W;
        float4* wsv = (float4*)ws;
        #pragma unroll
        for (int i = 0; i < 8; i++) wsv[i * 128 + tid] = Wv[i * 128 + tid];
    }
    // load my row of X, store transposed (conflict-free STS; L1 buffers the strided LDG)
    {
        int row = row0 + tid;
        if (row < N) {
            const float4* Xv = (const float4*)(X + (size_t)row * CDIM);
            #pragma unroll
            for (int j = 0; j < 16; j++) {
                float4 v = Xv[j];
                xT[(4 * j + 0) * 128 + tid] = v.x;
                xT[(4 * j + 1) * 128 + tid] = v.y;
                xT[(4 * j + 2) * 128 + tid] = v.z;
                xT[(4 * j + 3) * 128 + tid] = v.w;
            }
        } else {
            #pragma unroll
            for (int j = 0; j < 64; j++) xT[j * 128 + tid] = 0.f;
        }
    }
    __syncthreads();

    const int ty = tid >> 3;   // 0..15 -> rows ty*8..ty*8+7
    const int tx = tid & 7;    // 0..7  -> cols tx*8..tx*8+7
    float acc[8][8];
    #pragma unroll
    for (int i = 0; i < 8; i++)
        #pragma unroll
        for (int j = 0; j < 8; j++) acc[i][j] = 0.f;

    #pragma unroll 8
    for (int k = 0; k < 64; k++) {
        float4 a0 = *(const float4*)&xT[k * 128 + ty * 8];
        float4 a1 = *(const float4*)&xT[k * 128 + ty * 8 + 4];
        float4 b0 = *(const float4*)&ws[k * 64 + tx * 8];
        float4 b1 = *(const float4*)&ws[k * 64 + tx * 8 + 4];
        float a[8] = {a0.x, a0.y, a0.z, a0.w, a1.x, a1.y, a1.z, a1.w};
        float b[8] = {b0.x, b0.y, b0.z, b0.w, b1.x, b1.y, b1.z, b1.w};
        #pragma unroll
        for (int i = 0; i < 8; i++)
            #pragma unroll
            for (int j = 0; j < 8; j++) acc[i][j] = fmaf(a[i], b[j], acc[i][j]);
    }

    float av[8];
    #pragma unroll
    for (int j = 0; j < 8; j++) av[j] = __ldg(&avs[tx * 8 + j]);

    #pragma unroll
    for (int i = 0; i < 8; i++) {
        int row = row0 + ty * 8 + i;
        float al = 0.f;
        #pragma unroll
        for (int j = 0; j < 8; j++) al = fmaf(acc[i][j], av[j], al);
        // reduce across the 8 lanes sharing this row (lane groups of 8, aligned)
        al += __shfl_down_sync(0xffffffffu, al, 4);
        al += __shfl_down_sync(0xffffffffu, al, 2);
        al += __shfl_down_sync(0xffffffffu, al, 1);
        if (row < N) {
            float4* Hp = (float4*)(H + (size_t)row * CDIM + tx * 8);
            Hp[0] = make_float4(acc[i][0], acc[i][1], acc[i][2], acc[i][3]);
            Hp[1] = make_float4(acc[i][4], acc[i][5], acc[i][6], acc[i][7]);
            if (tx == 0) als[row] = al;
        }
    }
}

// al_d = X @ wvec   (warp per row, coalesced float2 loads)
__global__ void matvec_kernel(const float* __restrict__ X, const float* __restrict__ wvec,
                              float* __restrict__ ald, int N) {
    __shared__ float wv[CDIM];
    int tid = threadIdx.x;
    if (tid < CDIM) wv[tid] = wvec[tid];
    __syncthreads();
    int warp = (blockIdx.x * blockDim.x + tid) >> 5;
    int lane = tid & 31;
    if (warp >= N) return;
    float2 x2 = ((const float2*)(X + (size_t)warp * CDIM))[lane];
    float s = fmaf(x2.x, wv[lane * 2], x2.y * wv[lane * 2 + 1]);
    #pragma unroll
    for (int o = 16; o > 0; o >>= 1) s += __shfl_down_sync(0xffffffffu, s, o);
    if (lane == 0) ald[warp] = s;
}

// out rows <- bias ; m <- enc(-inf) ; den <- 0
__global__ void init_kernel(float* __restrict__ out, const float* __restrict__ bias,
                            unsigned* __restrict__ m, float* __restrict__ den, int Nd) {
    long i = (long)blockIdx.x * blockDim.x + threadIdx.x;
    long total = (long)Nd * CDIM;
    if (i < total) out[i] = __ldg(&bias[i & 63]);
    if (i < Nd) {
        m[i] = 0x007FFFFFu;   // fenc(-inf)
        den[i] = 0.f;
    }
}

// pass A: e = leaky_relu(als[src]+ald[dst], 0.2); segment max via atomicMax on encoded uint
__global__ void edgeA_kernel(const int* __restrict__ src, const int* __restrict__ dst,
                             const float* __restrict__ als, const float* __restrict__ ald,
                             unsigned* __restrict__ m, float* __restrict__ ebuf, int E) {
    int i = blockIdx.x * blockDim.x + threadIdx.x;
    if (i >= E) return;
    int d = __ldg(&dst[i]);
    float v = __ldg(&als[__ldg(&src[i])]) + __ldg(&ald[d]);
    v = (v >= 0.f) ? v : 0.2f * v;
    ebuf[i] = v;
    atomicMax(&m[d], fenc(v));
}

// pass B: ex = exp(e - m[dst]); den[dst] += ex
__global__ void edgeB_kernel(const int* __restrict__ dst, const unsigned* __restrict__ m,
                             float* __restrict__ den, float* __restrict__ ebuf, int E) {
    int i = blockIdx.x * blockDim.x + threadIdx.x;
    if (i >= E) return;
    int d = __ldg(&dst[i]);
    float ex = __expf(ebuf[i] - fdec(__ldg(&m[d])));
    ebuf[i] = ex;
    atomicAdd(&den[d], ex);
}

// pass C: out[dst] += (ex/den[dst]) * hs[src]   — 16 threads per edge, float4 vector reds
__global__ void edgeC_kernel(const int* __restrict__ src, const int* __restrict__ dst,
                             const float* __restrict__ ebuf, const float* __restrict__ den,
                             const float* __restrict__ hs, float* __restrict__ out, int E) {
    long t = (long)blockIdx.x * blockDim.x + threadIdx.x;
    int e = (int)(t >> 4);
    if (e >= E) return;
    int part = (int)(t & 15);
    int s = __ldg(&src[e]);
    int d = __ldg(&dst[e]);
    float alpha = __ldg(&ebuf[e]) / __ldg(&den[d]);
    float4 h = __ldg((const float4*)(hs + (size_t)s * CDIM) + part);
    float4 v = make_float4(alpha * h.x, alpha * h.y, alpha * h.z, alpha * h.w);
    atomicAdd((float4*)(out + (size_t)d * CDIM + part * 4), v);
}

// in-place ELU
__global__ void elu_kernel(float* __restrict__ p, long n) {
    long i = (long)blockIdx.x * blockDim.x + threadIdx.x;
    if (i >= n) return;
    float v = p[i];
    p[i] = (v > 0.f) ? v : expm1f(v);
}

// ------------------------- host orchestration -------------------------
static void run_conv(const float* x_src, int Ns, const float* x_dst, int Nd,
                     const int* src, const int* dst, int E,
                     const float* Ws, const float* Wd,
                     const float* avs, const float* avd, const float* b,
                     float* out,
                     float* hs, float* als, float* ald, unsigned* m, float* den,
                     float* ebuf, float* wvec)
{
    wvec_kernel<<<1, 64>>>(Wd, avd, wvec);
    gemm_als_kernel<<<(Ns + 127) / 128, 128>>>(x_src, Ws, avs, hs, als, Ns);
    matvec_kernel<<<(Nd + 7) / 8, 256>>>(x_dst, wvec, ald, Nd);
    long tot = (long)Nd * CDIM;
    init_kernel<<<(unsigned)((tot + 255) / 256), 256>>>(out, b, m, den, Nd);
    edgeA_kernel<<<(E + 255) / 256, 256>>>(src, dst, als, ald, m, ebuf, E);
    edgeB_kernel<<<(E + 255) / 256, 256>>>(dst, m, den, ebuf, E);
    long tc = (long)E * 16;
    edgeC_kernel<<<(unsigned)((tc + 255) / 256), 256>>>(src, dst, ebuf, den, hs, out, E);
}

extern "C" void kernel_launch(void* const* d_in, const int* in_sizes, int n_in,
                              void* d_out, int out_size)
{
    const float* xp   = (const float*)d_in[0];
    const float* xq   = (const float*)d_in[1];
    const int*   pv_s = (const int*)d_in[2];
    const int*   pv_d = (const int*)d_in[3];
    const int*   vp_s = (const int*)d_in[4];
    const int*   vp_d = (const int*)d_in[5];
    const float* Wsrc = (const float*)d_in[6];
    const float* Wdst = (const float*)d_in[7];
    const float* asrc = (const float*)d_in[8];
    const float* adst = (const float*)d_in[9];
    const float* bias = (const float*)d_in[10];
    int E = in_sizes[2];

    float *hs, *hp1, *hq1, *als, *ald, *den, *ebuf, *wvec;
    unsigned* m;
    cudaGetSymbolAddress((void**)&hs,   g_hs);
    cudaGetSymbolAddress((void**)&hp1,  g_hp1);
    cudaGetSymbolAddress((void**)&hq1,  g_hq1);
    cudaGetSymbolAddress((void**)&als,  g_als);
    cudaGetSymbolAddress((void**)&ald,  g_ald);
    cudaGetSymbolAddress((void**)&m,    g_m);
    cudaGetSymbolAddress((void**)&den,  g_den);
    cudaGetSymbolAddress((void**)&ebuf, g_e);
    cudaGetSymbolAddress((void**)&wvec, g_wvec);

    float* outp = (float*)d_out;                         // persons  [NP*64]
    float* outq = (float*)d_out + (size_t)NP * CDIM;     // products [NQ*64]

    // ---- layer 0 ----
    // edge type 0: Person->Product (dst=Product)
    run_conv(xp, NP, xq, NQ, pv_s, pv_d, E,
             Wsrc + 0 * 4096, Wdst + 0 * 4096, asrc + 0 * 64, adst + 0 * 64, bias + 0 * 64,
             hq1, hs, als, ald, m, den, ebuf, wvec);
    // edge type 1: Product->Person (dst=Person), inputs are OLD hp/hq
    run_conv(xq, NQ, xp, NP, vp_s, vp_d, E,
             Wsrc + 1 * 4096, Wdst + 1 * 4096, asrc + 1 * 64, adst + 1 * 64, bias + 1 * 64,
             hp1, hs, als, ald, m, den, ebuf, wvec);
    elu_kernel<<<(unsigned)(((long)NP * CDIM + 255) / 256), 256>>>(hp1, (long)NP * CDIM);
    elu_kernel<<<(unsigned)(((long)NQ * CDIM + 255) / 256), 256>>>(hq1, (long)NQ * CDIM);

    // ---- layer 1 (write conv outputs directly into d_out) ----
    run_conv(hp1, NP, hq1, NQ, pv_s, pv_d, E,
             Wsrc + 2 * 4096, Wdst + 2 * 4096, asrc + 2 * 64, adst + 2 * 64, bias + 2 * 64,
             outq, hs, als, ald, m, den, ebuf, wvec);
    run_conv(hq1, NQ, hp1, NP, vp_s, vp_d, E,
             Wsrc + 3 * 4096, Wdst + 3 * 4096, asrc + 3 * 64, adst + 3 * 64, bias + 3 * 64,
             outp, hs, als, ald, m, den, ebuf, wvec);
    // final ELU (reference applies elu to both outputs at the end)
    elu_kernel<<<(unsigned)(((long)NP * CDIM + 255) / 256), 256>>>(outp, (long)NP * CDIM);
    elu_kernel<<<(unsigned)(((long)NQ * CDIM + 255) / 256), 256>>>(outq, (long)NQ * CDIM);
}